// round 12
// baseline (speedup 1.0000x reference)
#include <cuda_runtime.h>
#include <cuda_fp16.h>
#include <math.h>
#include <stdint.h>

// Problem constants
#define BB_    4
#define TT_    4096
#define EE_    1024
#define DFF_   4096
#define CH_    64
#define ST_    32
#define NCHUNK 128
#define ROWS_  (BB_ * CH_)   // 256
#define TPAD_  (TT_ + ST_)   // 4128

// GEMM smem: 2 arrays (A, B), 128 rows x 64 k fp16, stride 144B, triple buf.
#define RS_     144
#define ABUF_   (128 * RS_)          // 18432
#define BUFSZ_  (2 * ABUF_)          // 36864
#define GSMEM_  (3 * BUFSZ_)         // 110592

// ================= helpers =================
__device__ __forceinline__ uint32_t smem_u32(const void* p) {
    uint32_t a;
    asm("{ .reg .u64 t; cvta.to.shared.u64 t, %1; cvt.u32.u64 %0, t; }"
        : "=r"(a) : "l"(p));
    return a;
}
__device__ __forceinline__ void cp16(uint32_t d, const void* s) {
    asm volatile("cp.async.cg.shared.global [%0], [%1], 16;" :: "r"(d), "l"(s) : "memory");
}
#define CP_COMMIT() asm volatile("cp.async.commit_group;" ::: "memory")
#define CP_WAIT0()  asm volatile("cp.async.wait_group 0;" ::: "memory")
#define CP_WAIT1()  asm volatile("cp.async.wait_group 1;" ::: "memory")
#define CP_WAIT2()  asm volatile("cp.async.wait_group 2;" ::: "memory")

__device__ __forceinline__ void ldmx4(uint32_t* r, uint32_t addr) {
    asm volatile("ldmatrix.sync.aligned.m8n8.x4.shared.b16 {%0,%1,%2,%3}, [%4];"
        : "=r"(r[0]), "=r"(r[1]), "=r"(r[2]), "=r"(r[3]) : "r"(addr));
}
__device__ __forceinline__ void mma16816(float* c, const uint32_t* a, const uint32_t* b) {
    asm volatile("mma.sync.aligned.m16n8k16.row.col.f32.f16.f16.f32 "
        "{%0,%1,%2,%3}, {%4,%5,%6,%7}, {%8,%9}, {%0,%1,%2,%3};"
        : "+f"(c[0]), "+f"(c[1]), "+f"(c[2]), "+f"(c[3])
        : "r"(a[0]), "r"(a[1]), "r"(a[2]), "r"(a[3]), "r"(b[0]), "r"(b[1]));
}
__device__ __forceinline__ uint32_t pk2h(__half a, __half b) {
    __half2 t = __halves2half2(a, b);
    return *(uint32_t*)&t;
}

// ================= device scratch =================
__device__ float g_M[CH_ * CH_];
__device__ float g_cn[BB_ * ST_ * EE_];        // LN1 of carry rows
__device__ float g_cnx[BB_ * TPAD_ * EE_];     // LN1 of all x rows (precomputed)
__device__ float g_res2[ROWS_ * EE_];          // fp32 res2 (residual path)
__device__ __align__(16) __half g_res2h[ROWS_ * EE_];   // fp16 res2 (GEMM A)
__device__ float2 g_pstat[ROWS_ * 16];         // per (row, e-slice) {sum, sumsq}
__device__ float g_u[2 * DFF_];                // sum_e w2*Wup
__device__ float g_vb[2 * DFF_];               // sum_e b2*Wup + b_up
__device__ float g_part[8 * ROWS_ * EE_];
__device__ __align__(16) __half g_f[ROWS_ * DFF_];
__device__ __align__(16) __half g_wup[2 * DFF_ * EE_];  // w2-folded, fp16
__device__ __align__(16) __half g_wdn[EE_ * DFF_];

// ================= setup kernels =================
__global__ void k_precompute_M(const float* __restrict__ w1,
                               const float* __restrict__ w2) {
    int idx = blockIdx.x * blockDim.x + threadIdx.x;
    int t = idx >> 6, s = idx & 63;
    float acc = 0.f;
    #pragma unroll
    for (int u = 0; u < 48; u++)
        acc += w2[t * 48 + u] * w1[u * 64 + s];
    g_M[idx] = acc;
}

__global__ void k_cvt(const float* __restrict__ src, __half* __restrict__ h) {
    int i = (blockIdx.x * blockDim.x + threadIdx.x) * 2;
    float2 v = *(const float2*)&src[i];
    *(uint32_t*)&h[i] = pk2h(__float2half_rn(v.x), __float2half_rn(v.y));
}

// convert up-weights with ln2_w folded in: W'[c,e] = Wup[c,e] * w2[e]
__global__ void k_cvt_up(const float* __restrict__ src, __half* __restrict__ h,
                         const float* __restrict__ w2) {
    int i = (blockIdx.x * blockDim.x + threadIdx.x) * 2;
    int e = i & (EE_ - 1);
    float2 v = *(const float2*)&src[i];
    float2 s = *(const float2*)&w2[e];
    *(uint32_t*)&h[i] = pk2h(__float2half_rn(v.x * s.x), __float2half_rn(v.y * s.y));
}

// u[c] = sum_e w2[e]*Wup[c,e]; vb[c] = sum_e b2[e]*Wup[c,e] + b_up[c]
__global__ __launch_bounds__(256) void k_uv(const float* __restrict__ wup,
                                            const float* __restrict__ w2,
                                            const float* __restrict__ b2,
                                            const float* __restrict__ bup) {
    int c = blockIdx.x * 8 + (threadIdx.x >> 5);
    int lane = threadIdx.x & 31;
    float u = 0.f, vb = 0.f;
    for (int e = lane; e < EE_; e += 32) {
        float wv = wup[(long)c * EE_ + e];
        u += w2[e] * wv;
        vb += b2[e] * wv;
    }
    #pragma unroll
    for (int o = 16; o > 0; o >>= 1) {
        u += __shfl_xor_sync(0xffffffffu, u, o);
        vb += __shfl_xor_sync(0xffffffffu, vb, o);
    }
    if (lane == 0) { g_u[c] = u; g_vb[c] = vb + bup[c]; }
}

// LN1 of every x row (incl. 32 pad rows of zeros), once per call.
__global__ __launch_bounds__(256) void k_lnx(const float* __restrict__ x,
                                             const float* __restrict__ w,
                                             const float* __restrict__ bia) {
    int rb = blockIdx.x;
    int b = rb / TPAD_, gt = rb % TPAD_;
    int tid = threadIdx.x;
    float4 v = (gt < TT_) ? *(const float4*)&x[((long)b * TT_ + gt) * EE_ + 4 * tid]
                          : make_float4(0.f, 0.f, 0.f, 0.f);
    float s = v.x + v.y + v.z + v.w;
    float s2 = v.x * v.x + v.y * v.y + v.z * v.z + v.w * v.w;
    __shared__ float ws[8], ws2[8];
    #pragma unroll
    for (int o = 16; o > 0; o >>= 1) {
        s += __shfl_xor_sync(0xffffffffu, s, o);
        s2 += __shfl_xor_sync(0xffffffffu, s2, o);
    }
    int warp = tid >> 5, lane = tid & 31;
    if (lane == 0) { ws[warp] = s; ws2[warp] = s2; }
    __syncthreads();
    if (tid < 32) {
        s = (lane < 8) ? ws[lane] : 0.f;
        s2 = (lane < 8) ? ws2[lane] : 0.f;
        #pragma unroll
        for (int o = 4; o > 0; o >>= 1) {
            s += __shfl_xor_sync(0xffffffffu, s, o);
            s2 += __shfl_xor_sync(0xffffffffu, s2, o);
        }
        if (lane == 0) { ws[0] = s; ws2[0] = s2; }
    }
    __syncthreads();
    float mu = ws[0] * (1.f / EE_);
    float var = ws2[0] * (1.f / EE_) - mu * mu;
    float rs = rsqrtf(var + 1e-5f);
    float4 wv = *(const float4*)&w[4 * tid];
    float4 bv = *(const float4*)&bia[4 * tid];
    float4 o;
    o.x = (v.x - mu) * rs * wv.x + bv.x;
    o.y = (v.y - mu) * rs * wv.y + bv.y;
    o.z = (v.z - mu) * rs * wv.z + bv.z;
    o.w = (v.w - mu) * rs * wv.w + bv.w;
    *(float4*)&g_cnx[(long)rb * EE_ + 4 * tid] = o;
}

// prime g_cn for step 0
__global__ void k_prime() {
    int idx = blockIdx.x * blockDim.x + threadIdx.x;
    int b = idx >> 15, rem = idx & 32767;
    int t = rem >> 10, e = rem & 1023;
    g_cn[(b * ST_ + t) * EE_ + e] = g_cnx[((long)b * TPAD_ + t) * EE_ + e];
}

// ====== temporal mix + residual + per-slice LN2 partial stats ============
// grid (4 batches, 16 e-slices of 64), 256 threads
__global__ __launch_bounds__(256) void k_fft2(const float* __restrict__ x, int step) {
    __shared__ float cns[64 * 64];
    __shared__ float Ms[64 * 64];
    __shared__ float sp1[4][16][2], sp2[4][16][2];
    int bb = blockIdx.x;
    int slice = blockIdx.y;
    int e0 = slice * 64;
    int tid = threadIdx.x;
    #pragma unroll
    for (int i = 0; i < 4; i++) {
        int f4 = tid + i * 256;
        int s = f4 >> 4, e = (f4 & 15) * 4;
        float4 v = (s < ST_)
            ? *(const float4*)&g_cn[(bb * ST_ + s) * EE_ + e0 + e]
            : *(const float4*)&g_cnx[((long)bb * TPAD_ + step * ST_ + s) * EE_ + e0 + e];
        *(float4*)&cns[s * 64 + e] = v;
        *(float4*)&Ms[f4 * 4] = *(const float4*)&g_M[f4 * 4];
    }
    __syncthreads();
    int e = tid & 63;
    int tg = tid >> 6;
    int lane = tid & 31;
    int wh = (tid >> 5) & 1;
    float cr[64];
    #pragma unroll
    for (int s = 0; s < 64; s++) cr[s] = cns[s * 64 + e];
    #pragma unroll
    for (int i = 0; i < 16; i++) {
        int t = tg * 16 + i;
        float a = 0.f;
        #pragma unroll
        for (int s4 = 0; s4 < 16; s4++) {
            float4 m = *(float4*)&Ms[t * 64 + s4 * 4];
            a += m.x * cr[4 * s4] + m.y * cr[4 * s4 + 1]
               + m.z * cr[4 * s4 + 2] + m.w * cr[4 * s4 + 3];
        }
        int gt = step * ST_ + t;
        float resid = (gt < TT_) ? x[((long)bb * TT_ + gt) * EE_ + e0 + e] : 0.f;
        float r2 = a + resid;
        g_res2[(bb * 64 + t) * EE_ + e0 + e] = r2;
        g_res2h[(bb * 64 + t) * EE_ + e0 + e] = __float2half_rn(r2);
        float s1 = r2, s2 = r2 * r2;
        #pragma unroll
        for (int o = 16; o > 0; o >>= 1) {
            s1 += __shfl_xor_sync(0xffffffffu, s1, o);
            s2 += __shfl_xor_sync(0xffffffffu, s2, o);
        }
        if (lane == 0) { sp1[tg][i][wh] = s1; sp2[tg][i][wh] = s2; }
    }
    __syncthreads();
    if (tid < 64) {
        int tg2 = tid >> 4, i2 = tid & 15;
        float s1 = sp1[tg2][i2][0] + sp1[tg2][i2][1];
        float s2 = sp2[tg2][i2][0] + sp2[tg2][i2][1];
        int row = bb * 64 + tg2 * 16 + i2;
        g_pstat[row * 16 + slice] = make_float2(s1, s2);
    }
}

// ===== UP GEMM (fp16, A=res2h, B=w2-folded Wup) + deferred-LN2 + sin-gate ==
__global__ __launch_bounds__(256) void k_up() {
    extern __shared__ char smem[];
    uint32_t sb = smem_u32(smem);
    int tid = threadIdx.x, wid = tid >> 5, l = tid & 31;
    int m0 = blockIdx.x * 128;
    int gn0 = blockIdx.y * 64;
    int wm = wid & 1, wn = wid >> 1;

    uint32_t aRow = (uint32_t)(wm * 64 + (l & 7) + ((l >> 3) & 1) * 8);
    uint32_t aCol = (uint32_t)(((l >> 4) & 1) * 16);
    uint32_t bRow = (uint32_t)(wn * 32 + (l & 7) + ((l >> 4) & 1) * 8);
    uint32_t bCol = (uint32_t)(((l >> 3) & 1) * 16);

    float acc[4][4][4] = {};

    auto load_chunk = [&](int c) {
        uint32_t base = sb + (uint32_t)((c % 3) * BUFSZ_);
        int k0 = c * 64;
        #pragma unroll
        for (int i = 0; i < 4; i++) {
            int idx = tid + i * 256;
            int r = idx >> 3, seg = idx & 7;
            uint32_t d0 = base + (uint32_t)(r * RS_ + seg * 16);
            cp16(d0, &g_res2h[(m0 + r) * EE_ + k0 + seg * 8]);
            int wr = (r & 1) ? (DFF_ + gn0 + (r >> 1)) : (gn0 + (r >> 1));
            cp16(d0 + ABUF_, &g_wup[(long)wr * EE_ + k0 + seg * 8]);
        }
        CP_COMMIT();
    };
    auto compute_chunk = [&](int c) {
        uint32_t ab = sb + (uint32_t)((c % 3) * BUFSZ_);
        #pragma unroll
        for (int k0 = 0; k0 < 64; k0 += 16) {
            uint32_t a[4][4], b[2][4];
            #pragma unroll
            for (int mt = 0; mt < 4; mt++)
                ldmx4(a[mt], ab + (aRow + mt * 16) * RS_ + k0 * 2 + aCol);
            #pragma unroll
            for (int np = 0; np < 2; np++)
                ldmx4(b[np], ab + ABUF_ + (bRow + np * 16) * RS_ + k0 * 2 + bCol);
            #pragma unroll
            for (int mt = 0; mt < 4; mt++)
                #pragma unroll
                for (int nt = 0; nt < 4; nt++)
                    mma16816(acc[mt][nt], a[mt], &b[nt >> 1][(nt & 1) * 2]);
        }
    };

    load_chunk(0); load_chunk(1);
    for (int c = 0; c < 16; c++) {
        if (c + 2 < 16) { load_chunk(c + 2); CP_WAIT2(); }
        else if (c + 1 < 16) CP_WAIT1();
        else CP_WAIT0();
        __syncthreads();
        compute_chunk(c);
        __syncthreads();
    }

    // row stats from per-slice partials
    float* muS = (float*)(smem + ABUF_);
    float* rsS = (float*)(smem + ABUF_ + 512);
    if (tid < 128) {
        float s1 = 0.f, s2 = 0.f;
        #pragma unroll
        for (int s = 0; s < 16; s++) {
            float2 p = g_pstat[(m0 + tid) * 16 + s];
            s1 += p.x; s2 += p.y;
        }
        float mu = s1 * (1.f / EE_);
        float var = s2 * (1.f / EE_) - mu * mu;
        muS[tid] = mu;
        rsS[tid] = rsqrtf(var + 1e-5f);
    }
    __syncthreads();

    // epilogue: deferred LN2 affine + sin-gate, stage via smem, coalesced out
    #pragma unroll
    for (int nt = 0; nt < 4; nt++) {
        int cl = wn * 16 + nt * 4 + (l & 3);
        float ug = g_u[gn0 + cl];
        float uv = g_u[DFF_ + gn0 + cl];
        float vg = g_vb[gn0 + cl];
        float vv = g_vb[DFF_ + gn0 + cl];
        #pragma unroll
        for (int mt = 0; mt < 4; mt++) {
            float* c = acc[mt][nt];
            int rl = wm * 64 + mt * 16 + (l >> 2);
            float mu0 = muS[rl], rs0 = rsS[rl];
            float mu1 = muS[rl + 8], rs1 = rsS[rl + 8];
            float fg0 = rs0 * (c[0] - mu0 * ug) + vg;
            float fv0 = rs0 * (c[1] - mu0 * uv) + vv;
            float fg1 = rs1 * (c[2] - mu1 * ug) + vg;
            float fv1 = rs1 * (c[3] - mu1 * uv) + vv;
            float f0 = __sinf(fg0) * fv0;
            float f1 = __sinf(fg1) * fv1;
            *(__half*)(smem + rl * RS_ + cl * 2) = __float2half_rn(f0);
            *(__half*)(smem + (rl + 8) * RS_ + cl * 2) = __float2half_rn(f1);
        }
    }
    __syncthreads();
    #pragma unroll
    for (int i = 0; i < 4; i++) {
        int idx = tid + i * 256;
        int r = idx >> 3, seg = idx & 7;
        uint4 vh = *(uint4*)(smem + r * RS_ + seg * 16);
        *(uint4*)&g_f[(long)(m0 + r) * DFF_ + gn0 + seg * 8] = vh;
    }
}

// ================= DOWN GEMM (fp16 1-product, split-K=8, 3-stage) ========
__global__ __launch_bounds__(256) void k_dn() {
    extern __shared__ char smem[];
    uint32_t sb = smem_u32(smem);
    int tid = threadIdx.x, wid = tid >> 5, l = tid & 31;
    int m0 = blockIdx.x * 128;
    int n0 = blockIdx.y * 128;
    int kz = blockIdx.z;
    int wm = wid & 1, wn = wid >> 1;

    uint32_t aRow = (uint32_t)(wm * 64 + (l & 7) + ((l >> 3) & 1) * 8);
    uint32_t aCol = (uint32_t)(((l >> 4) & 1) * 16);
    uint32_t bRow = (uint32_t)(wn * 32 + (l & 7) + ((l >> 4) & 1) * 8);
    uint32_t bCol = (uint32_t)(((l >> 3) & 1) * 16);

    float acc[4][4][4] = {};

    auto load_chunk = [&](int c) {
        uint32_t base = sb + (uint32_t)((c % 3) * BUFSZ_);
        int k0 = kz * 512 + c * 64;
        #pragma unroll
        for (int i = 0; i < 4; i++) {
            int idx = tid + i * 256;
            int r = idx >> 3, seg = idx & 7;
            uint32_t d0 = base + (uint32_t)(r * RS_ + seg * 16);
            cp16(d0, &g_f[(long)(m0 + r) * DFF_ + k0 + seg * 8]);
            cp16(d0 + ABUF_, &g_wdn[(long)(n0 + r) * DFF_ + k0 + seg * 8]);
        }
        CP_COMMIT();
    };
    auto compute_chunk = [&](int c) {
        uint32_t ab = sb + (uint32_t)((c % 3) * BUFSZ_);
        #pragma unroll
        for (int k0 = 0; k0 < 64; k0 += 16) {
            uint32_t a[4][4], b[2][4];
            #pragma unroll
            for (int mt = 0; mt < 4; mt++)
                ldmx4(a[mt], ab + (aRow + mt * 16) * RS_ + k0 * 2 + aCol);
            #pragma unroll
            for (int np = 0; np < 2; np++)
                ldmx4(b[np], ab + ABUF_ + (bRow + np * 16) * RS_ + k0 * 2 + bCol);
            #pragma unroll
            for (int mt = 0; mt < 4; mt++)
                #pragma unroll
                for (int nt = 0; nt < 4; nt++)
                    mma16816(acc[mt][nt], a[mt], &b[nt >> 1][(nt & 1) * 2]);
        }
    };

    load_chunk(0); load_chunk(1);
    for (int c = 0; c < 8; c++) {
        if (c + 2 < 8) { load_chunk(c + 2); CP_WAIT2(); }
        else if (c + 1 < 8) CP_WAIT1();
        else CP_WAIT0();
        __syncthreads();
        compute_chunk(c);
        __syncthreads();
    }

    float* dst = &g_part[(long)kz * (ROWS_ * EE_)];
    #pragma unroll
    for (int mt = 0; mt < 4; mt++)
        #pragma unroll
        for (int nt = 0; nt < 4; nt++) {
            float* c = acc[mt][nt];
            int col = n0 + wn * 32 + nt * 8 + (l & 3) * 2;
            int r0 = m0 + wm * 64 + mt * 16 + (l >> 2);
            *(float2*)&dst[(long)r0 * EE_ + col] = make_float2(c[0], c[1]);
            *(float2*)&dst[(long)(r0 + 8) * EE_ + col] = make_float2(c[2], c[3]);
        }
}

// ============ reduce: partials + bias + res2 -> out / LN1(carry) ==========
__global__ __launch_bounds__(256) void k_reduce_ln(const float* __restrict__ b_down,
                                                   const float* __restrict__ ln1w,
                                                   const float* __restrict__ ln1b,
                                                   float* __restrict__ out, int step) {
    int row = blockIdx.x;
    int bb = row >> 6, t = row & 63;
    int tid = threadIdx.x;
    int e = tid * 4;
    float4 v = *(const float4*)&g_part[row * EE_ + e];
    #pragma unroll
    for (int p = 1; p < 8; p++) {
        float4 q = *(const float4*)&g_part[(long)p * ROWS_ * EE_ + row * EE_ + e];
        v.x += q.x; v.y += q.y; v.z += q.z; v.w += q.w;
    }
    float4 r2 = *(const float4*)&g_res2[row * EE_ + e];
    float4 bd = *(const float4*)&b_down[e];
    v.x += r2.x + bd.x; v.y += r2.y + bd.y;
    v.z += r2.z + bd.z; v.w += r2.w + bd.w;
    if (t < ST_) {
        *(float4*)&out[((long)bb * TT_ + step * ST_ + t) * EE_ + e] = v;
    } else {
        float s = v.x + v.y + v.z + v.w;
        float s2 = v.x * v.x + v.y * v.y + v.z * v.z + v.w * v.w;
        __shared__ float ws[8], ws2[8];
        #pragma unroll
        for (int o = 16; o > 0; o >>= 1) {
            s += __shfl_xor_sync(0xffffffffu, s, o);
            s2 += __shfl_xor_sync(0xffffffffu, s2, o);
        }
        int warp = tid >> 5, lane = tid & 31;
        if (lane == 0) { ws[warp] = s; ws2[warp] = s2; }
        __syncthreads();
        if (tid < 32) {
            s = (lane < 8) ? ws[lane] : 0.f;
            s2 = (lane < 8) ? ws2[lane] : 0.f;
            #pragma unroll
            for (int o = 4; o > 0; o >>= 1) {
                s += __shfl_xor_sync(0xffffffffu, s, o);
                s2 += __shfl_xor_sync(0xffffffffu, s2, o);
            }
            if (lane == 0) { ws[0] = s; ws2[0] = s2; }
        }
        __syncthreads();
        float mu = ws[0] * (1.f / EE_);
        float var = ws2[0] * (1.f / EE_) - mu * mu;
        float rs = rsqrtf(var + 1e-5f);
        float4 wv = *(const float4*)&ln1w[e];
        float4 bv = *(const float4*)&ln1b[e];
        float4 o;
        o.x = (v.x - mu) * rs * wv.x + bv.x;
        o.y = (v.y - mu) * rs * wv.y + bv.y;
        o.z = (v.z - mu) * rs * wv.z + bv.z;
        o.w = (v.w - mu) * rs * wv.w + bv.w;
        *(float4*)&g_cn[(bb * ST_ + (t - ST_)) * EE_ + e] = o;
    }
}

// ================= launch =================
extern "C" void kernel_launch(void* const* d_in, const int* in_sizes, int n_in,
                              void* d_out, int out_size) {
    (void)in_sizes; (void)n_in; (void)out_size;
    const float* x      = (const float*)d_in[0];
    const float* ln1_w  = (const float*)d_in[1];
    const float* ln1_b  = (const float*)d_in[2];
    const float* w_fft1 = (const float*)d_in[3];
    const float* w_fft2 = (const float*)d_in[4];
    const float* ln2_w  = (const float*)d_in[5];
    const float* ln2_b  = (const float*)d_in[6];
    const float* w_up   = (const float*)d_in[7];
    const float* b_up   = (const float*)d_in[8];
    const float* w_down = (const float*)d_in[9];
    const float* b_down = (const float*)d_in[10];
    float* out = (float*)d_out;

    cudaFuncSetAttribute(k_up, cudaFuncAttributeMaxDynamicSharedMemorySize, GSMEM_);
    cudaFuncSetAttribute(k_dn, cudaFuncAttributeMaxDynamicSharedMemorySize, GSMEM_);

    __half *wup, *wdn;
    cudaGetSymbolAddress((void**)&wup, g_wup);
    cudaGetSymbolAddress((void**)&wdn, g_wdn);
    k_cvt_up<<<(2 * DFF_ * EE_) / 512, 256>>>(w_up, wup, ln2_w);
    k_cvt<<<(EE_ * DFF_) / 512, 256>>>(w_down, wdn);
    k_uv<<<1024, 256>>>(w_up, ln2_w, ln2_b, b_up);
    k_precompute_M<<<16, 256>>>(w_fft1, w_fft2);
    k_lnx<<<BB_ * TPAD_, 256>>>(x, ln1_w, ln1_b);
    k_prime<<<512, 256>>>();

    for (int i = 0; i < NCHUNK; i++) {
        k_fft2<<<dim3(BB_, 16), 256>>>(x, i);
        k_up<<<dim3(2, 64), 256, GSMEM_>>>();
        k_dn<<<dim3(2, 8, 8), 256, GSMEM_>>>();
        k_reduce_ln<<<ROWS_, 256>>>(b_down, ln1_w, ln1_b, out, i);
    }
}

// round 13
// speedup vs baseline: 1.0804x; 1.0804x over previous
#include <cuda_runtime.h>
#include <cuda_fp16.h>
#include <math.h>
#include <stdint.h>

// Problem constants
#define BB_    4
#define TT_    4096
#define EE_    1024
#define DFF_   4096
#define CH_    64
#define ST_    32
#define NCHUNK 128
#define ROWS_  (BB_ * CH_)   // 256
#define TPAD_  (TT_ + ST_)   // 4128

// GEMM smem: 2 arrays (A, B), 128 rows x 64 k fp16, stride 144B,
// TRIPLE buffered.
#define RS_     144
#define ABUF_   (128 * RS_)          // 18432
#define BUFSZ_  (2 * ABUF_)          // 36864
#define GSMEM_  (3 * BUFSZ_)         // 110592

// ================= helpers =================
__device__ __forceinline__ uint32_t smem_u32(const void* p) {
    uint32_t a;
    asm("{ .reg .u64 t; cvta.to.shared.u64 t, %1; cvt.u32.u64 %0, t; }"
        : "=r"(a) : "l"(p));
    return a;
}
__device__ __forceinline__ void cp16(uint32_t d, const void* s) {
    asm volatile("cp.async.cg.shared.global [%0], [%1], 16;" :: "r"(d), "l"(s) : "memory");
}
#define CP_COMMIT() asm volatile("cp.async.commit_group;" ::: "memory")
#define CP_WAIT0()  asm volatile("cp.async.wait_group 0;" ::: "memory")
#define CP_WAIT1()  asm volatile("cp.async.wait_group 1;" ::: "memory")
#define CP_WAIT2()  asm volatile("cp.async.wait_group 2;" ::: "memory")

__device__ __forceinline__ void ldmx4(uint32_t* r, uint32_t addr) {
    asm volatile("ldmatrix.sync.aligned.m8n8.x4.shared.b16 {%0,%1,%2,%3}, [%4];"
        : "=r"(r[0]), "=r"(r[1]), "=r"(r[2]), "=r"(r[3]) : "r"(addr));
}
__device__ __forceinline__ void mma16816(float* c, const uint32_t* a, const uint32_t* b) {
    asm volatile("mma.sync.aligned.m16n8k16.row.col.f32.f16.f16.f32 "
        "{%0,%1,%2,%3}, {%4,%5,%6,%7}, {%8,%9}, {%0,%1,%2,%3};"
        : "+f"(c[0]), "+f"(c[1]), "+f"(c[2]), "+f"(c[3])
        : "r"(a[0]), "r"(a[1]), "r"(a[2]), "r"(a[3]), "r"(b[0]), "r"(b[1]));
}
__device__ __forceinline__ uint32_t pk2h(__half a, __half b) {
    __half2 t = __halves2half2(a, b);
    return *(uint32_t*)&t;
}

// ================= device scratch =================
__device__ float g_M[CH_ * CH_];
__device__ float g_cn[BB_ * ST_ * EE_];        // LN1 of carry rows
__device__ float g_cnx[BB_ * TPAD_ * EE_];     // LN1 of all x rows (precomputed)
__device__ float g_res2[ROWS_ * EE_];
__device__ float g_part[8 * ROWS_ * EE_];
__device__ __align__(16) __half g_cn2[ROWS_ * EE_];       // LN2 out, fp16 rn
__device__ __align__(16) __half g_f[ROWS_ * DFF_];        // sin-gate out, fp16 rn
__device__ __align__(16) __half g_wup[2 * DFF_ * EE_];
__device__ __align__(16) __half g_wdn[EE_ * DFF_];

// ================= setup kernels =================
__global__ void k_precompute_M(const float* __restrict__ w1,
                               const float* __restrict__ w2) {
    int idx = blockIdx.x * blockDim.x + threadIdx.x;
    int t = idx >> 6, s = idx & 63;
    float acc = 0.f;
    #pragma unroll
    for (int u = 0; u < 48; u++)
        acc += w2[t * 48 + u] * w1[u * 64 + s];
    g_M[idx] = acc;
}

__global__ void k_cvt(const float* __restrict__ src, __half* __restrict__ h) {
    int i = (blockIdx.x * blockDim.x + threadIdx.x) * 2;
    float2 v = *(const float2*)&src[i];
    *(uint32_t*)&h[i] = pk2h(__float2half_rn(v.x), __float2half_rn(v.y));
}

// LN1 of every x row (incl. 32 pad rows of zeros), once per call.
__global__ __launch_bounds__(256) void k_lnx(const float* __restrict__ x,
                                             const float* __restrict__ w,
                                             const float* __restrict__ bia) {
    int rb = blockIdx.x;                 // b * TPAD_ + gt
    int b = rb / TPAD_, gt = rb % TPAD_;
    int tid = threadIdx.x;
    float4 v = (gt < TT_) ? *(const float4*)&x[((long)b * TT_ + gt) * EE_ + 4 * tid]
                          : make_float4(0.f, 0.f, 0.f, 0.f);
    float s = v.x + v.y + v.z + v.w;
    float s2 = v.x * v.x + v.y * v.y + v.z * v.z + v.w * v.w;
    __shared__ float ws[8], ws2[8];
    #pragma unroll
    for (int o = 16; o > 0; o >>= 1) {
        s += __shfl_xor_sync(0xffffffffu, s, o);
        s2 += __shfl_xor_sync(0xffffffffu, s2, o);
    }
    int warp = tid >> 5, lane = tid & 31;
    if (lane == 0) { ws[warp] = s; ws2[warp] = s2; }
    __syncthreads();
    if (tid < 32) {
        s = (lane < 8) ? ws[lane] : 0.f;
        s2 = (lane < 8) ? ws2[lane] : 0.f;
        #pragma unroll
        for (int o = 4; o > 0; o >>= 1) {
            s += __shfl_xor_sync(0xffffffffu, s, o);
            s2 += __shfl_xor_sync(0xffffffffu, s2, o);
        }
        if (lane == 0) { ws[0] = s; ws2[0] = s2; }
    }
    __syncthreads();
    float mu = ws[0] * (1.f / EE_);
    float var = ws2[0] * (1.f / EE_) - mu * mu;
    float rs = rsqrtf(var + 1e-5f);
    float4 wv = *(const float4*)&w[4 * tid];
    float4 bv = *(const float4*)&bia[4 * tid];
    float4 o;
    o.x = (v.x - mu) * rs * wv.x + bv.x;
    o.y = (v.y - mu) * rs * wv.y + bv.y;
    o.z = (v.z - mu) * rs * wv.z + bv.z;
    o.w = (v.w - mu) * rs * wv.w + bv.w;
    *(float4*)&g_cnx[(long)rb * EE_ + 4 * tid] = o;
}

// prime g_cn for step 0
__global__ void k_prime() {
    int idx = blockIdx.x * blockDim.x + threadIdx.x;
    int b = idx >> 15, rem = idx & 32767;
    int t = rem >> 10, e = rem & 1023;
    g_cn[(b * ST_ + t) * EE_ + e] = g_cnx[((long)b * TPAD_ + t) * EE_ + e];
}

// ================= temporal mix + residual (e-sliced, smem-staged) =======
__global__ __launch_bounds__(256) void k_fft(const float* __restrict__ x, int step) {
    __shared__ float cns[64 * 64];
    __shared__ float Ms[64 * 64];
    int bb = blockIdx.x;
    int e0 = blockIdx.y * 64;
    int tid = threadIdx.x;
    #pragma unroll
    for (int i = 0; i < 4; i++) {
        int f4 = tid + i * 256;
        int s = f4 >> 4, e = (f4 & 15) * 4;
        float4 v = (s < ST_)
            ? *(const float4*)&g_cn[(bb * ST_ + s) * EE_ + e0 + e]
            : *(const float4*)&g_cnx[((long)bb * TPAD_ + step * ST_ + s) * EE_ + e0 + e];
        *(float4*)&cns[s * 64 + e] = v;
        *(float4*)&Ms[f4 * 4] = *(const float4*)&g_M[f4 * 4];
    }
    __syncthreads();
    int e = tid & 63;
    int tg = tid >> 6;
    float cr[64];
    #pragma unroll
    for (int s = 0; s < 64; s++) cr[s] = cns[s * 64 + e];
    #pragma unroll
    for (int i = 0; i < 16; i++) {
        int t = tg * 16 + i;
        float a = 0.f;
        #pragma unroll
        for (int s4 = 0; s4 < 16; s4++) {
            float4 m = *(float4*)&Ms[t * 64 + s4 * 4];
            a += m.x * cr[4 * s4] + m.y * cr[4 * s4 + 1] + m.z * cr[4 * s4 + 2] + m.w * cr[4 * s4 + 3];
        }
        int gt = step * ST_ + t;
        float resid = (gt < TT_) ? x[((long)bb * TT_ + gt) * EE_ + e0 + e] : 0.f;
        g_res2[(bb * 64 + t) * EE_ + e0 + e] = a + resid;
    }
}

// ================= LN2 (emits fp16 rn) =================
__global__ __launch_bounds__(256) void k_ln2(const float* __restrict__ w,
                                             const float* __restrict__ bia) {
    int row = blockIdx.x;
    int tid = threadIdx.x;
    float4 v = *(const float4*)&g_res2[row * EE_ + 4 * tid];
    float s = v.x + v.y + v.z + v.w;
    float s2 = v.x * v.x + v.y * v.y + v.z * v.z + v.w * v.w;
    __shared__ float ws[8], ws2[8];
    #pragma unroll
    for (int o = 16; o > 0; o >>= 1) {
        s += __shfl_xor_sync(0xffffffffu, s, o);
        s2 += __shfl_xor_sync(0xffffffffu, s2, o);
    }
    int warp = tid >> 5, lane = tid & 31;
    if (lane == 0) { ws[warp] = s; ws2[warp] = s2; }
    __syncthreads();
    if (tid < 32) {
        s = (lane < 8) ? ws[lane] : 0.f;
        s2 = (lane < 8) ? ws2[lane] : 0.f;
        #pragma unroll
        for (int o = 4; o > 0; o >>= 1) {
            s += __shfl_xor_sync(0xffffffffu, s, o);
            s2 += __shfl_xor_sync(0xffffffffu, s2, o);
        }
        if (lane == 0) { ws[0] = s; ws2[0] = s2; }
    }
    __syncthreads();
    float mu = ws[0] * (1.f / EE_);
    float var = ws2[0] * (1.f / EE_) - mu * mu;
    float rs = rsqrtf(var + 1e-5f);
    float4 wv = *(const float4*)&w[4 * tid];
    float4 bv = *(const float4*)&bia[4 * tid];
    float o0 = (v.x - mu) * rs * wv.x + bv.x;
    float o1 = (v.y - mu) * rs * wv.y + bv.y;
    float o2 = (v.z - mu) * rs * wv.z + bv.z;
    float o3 = (v.w - mu) * rs * wv.w + bv.w;
    *(uint2*)&g_cn2[row * EE_ + 4 * tid] =
        make_uint2(pk2h(__float2half_rn(o0), __float2half_rn(o1)),
                   pk2h(__float2half_rn(o2), __float2half_rn(o3)));
}

// ================= UP GEMM (fp16 1-product, 3-stage) + sin-gate ==========
// buffer layout: A at 0, B at ABUF_
__global__ __launch_bounds__(256) void k_up(const float* __restrict__ b_up) {
    extern __shared__ char smem[];
    uint32_t sb = smem_u32(smem);
    int tid = threadIdx.x, wid = tid >> 5, l = tid & 31;
    int m0 = blockIdx.x * 128;
    int gn0 = blockIdx.y * 64;
    int wm = wid & 1, wn = wid >> 1;

    uint32_t aRow = (uint32_t)(wm * 64 + (l & 7) + ((l >> 3) & 1) * 8);
    uint32_t aCol = (uint32_t)(((l >> 4) & 1) * 16);
    uint32_t bRow = (uint32_t)(wn * 32 + (l & 7) + ((l >> 4) & 1) * 8);
    uint32_t bCol = (uint32_t)(((l >> 3) & 1) * 16);

    float acc[4][4][4] = {};

    auto load_chunk = [&](int c) {
        uint32_t base = sb + (uint32_t)((c % 3) * BUFSZ_);
        int k0 = c * 64;
        #pragma unroll
        for (int i = 0; i < 4; i++) {
            int idx = tid + i * 256;
            int r = idx >> 3, seg = idx & 7;
            uint32_t d0 = base + (uint32_t)(r * RS_ + seg * 16);
            cp16(d0, &g_cn2[(m0 + r) * EE_ + k0 + seg * 8]);
            int wr = (r & 1) ? (DFF_ + gn0 + (r >> 1)) : (gn0 + (r >> 1));
            cp16(d0 + ABUF_, &g_wup[(long)wr * EE_ + k0 + seg * 8]);
        }
        CP_COMMIT();
    };
    auto compute_chunk = [&](int c) {
        uint32_t ab = sb + (uint32_t)((c % 3) * BUFSZ_);
        #pragma unroll
        for (int k0 = 0; k0 < 64; k0 += 16) {
            uint32_t a[4][4], b[2][4];
            #pragma unroll
            for (int mt = 0; mt < 4; mt++)
                ldmx4(a[mt], ab + (aRow + mt * 16) * RS_ + k0 * 2 + aCol);
            #pragma unroll
            for (int np = 0; np < 2; np++)
                ldmx4(b[np], ab + ABUF_ + (bRow + np * 16) * RS_ + k0 * 2 + bCol);
            #pragma unroll
            for (int mt = 0; mt < 4; mt++)
                #pragma unroll
                for (int nt = 0; nt < 4; nt++)
                    mma16816(acc[mt][nt], a[mt], &b[nt >> 1][(nt & 1) * 2]);
        }
    };

    load_chunk(0); load_chunk(1);
    for (int c = 0; c < 16; c++) {
        if (c + 2 < 16) { load_chunk(c + 2); CP_WAIT2(); }
        else if (c + 1 < 16) CP_WAIT1();
        else CP_WAIT0();
        __syncthreads();
        compute_chunk(c);
        __syncthreads();
    }

    // epilogue: sin-gate, stage via smem, coalesced out
    #pragma unroll
    for (int nt = 0; nt < 4; nt++) {
        int cl = wn * 16 + nt * 4 + (l & 3);
        float bg = b_up[gn0 + cl];
        float bv = b_up[DFF_ + gn0 + cl];
        #pragma unroll
        for (int mt = 0; mt < 4; mt++) {
            float* c = acc[mt][nt];
            int rl = wm * 64 + mt * 16 + (l >> 2);
            float f0 = __sinf(c[0] + bg) * (c[1] + bv);
            float f1 = __sinf(c[2] + bg) * (c[3] + bv);
            *(__half*)(smem + rl * RS_ + cl * 2) = __float2half_rn(f0);
            *(__half*)(smem + (rl + 8) * RS_ + cl * 2) = __float2half_rn(f1);
        }
    }
    __syncthreads();
    #pragma unroll
    for (int i = 0; i < 4; i++) {
        int idx = tid + i * 256;
        int r = idx >> 3, seg = idx & 7;
        uint4 vh = *(uint4*)(smem + r * RS_ + seg * 16);
        *(uint4*)&g_f[(long)(m0 + r) * DFF_ + gn0 + seg * 8] = vh;
    }
}

// ================= DOWN GEMM (fp16 1-product, split-K=8, 3-stage) ========
__global__ __launch_bounds__(256) void k_dn() {
    extern __shared__ char smem[];
    uint32_t sb = smem_u32(smem);
    int tid = threadIdx.x, wid = tid >> 5, l = tid & 31;
    int m0 = blockIdx.x * 128;
    int n0 = blockIdx.y * 128;
    int kz = blockIdx.z;
    int wm = wid & 1, wn = wid >> 1;

    uint32_t aRow = (uint32_t)(wm * 64 + (l & 7) + ((l >> 3) & 1) * 8);
    uint32_t aCol = (uint32_t)(((l >> 4) & 1) * 16);
    uint32_t bRow = (uint32_t)(wn * 32 + (l & 7) + ((l >> 4) & 1) * 8);
    uint32_t bCol = (uint32_t)(((l >> 3) & 1) * 16);

    float acc[4][4][4] = {};

    auto load_chunk = [&](int c) {
        uint32_t base = sb + (uint32_t)((c % 3) * BUFSZ_);
        int k0 = kz * 512 + c * 64;
        #pragma unroll
        for (int i = 0; i < 4; i++) {
            int idx = tid + i * 256;
            int r = idx >> 3, seg = idx & 7;
            uint32_t d0 = base + (uint32_t)(r * RS_ + seg * 16);
            cp16(d0, &g_f[(long)(m0 + r) * DFF_ + k0 + seg * 8]);
            cp16(d0 + ABUF_, &g_wdn[(long)(n0 + r) * DFF_ + k0 + seg * 8]);
        }
        CP_COMMIT();
    };
    auto compute_chunk = [&](int c) {
        uint32_t ab = sb + (uint32_t)((c % 3) * BUFSZ_);
        #pragma unroll
        for (int k0 = 0; k0 < 64; k0 += 16) {
            uint32_t a[4][4], b[2][4];
            #pragma unroll
            for (int mt = 0; mt < 4; mt++)
                ldmx4(a[mt], ab + (aRow + mt * 16) * RS_ + k0 * 2 + aCol);
            #pragma unroll
            for (int np = 0; np < 2; np++)
                ldmx4(b[np], ab + ABUF_ + (bRow + np * 16) * RS_ + k0 * 2 + bCol);
            #pragma unroll
            for (int mt = 0; mt < 4; mt++)
                #pragma unroll
                for (int nt = 0; nt < 4; nt++)
                    mma16816(acc[mt][nt], a[mt], &b[nt >> 1][(nt & 1) * 2]);
        }
    };

    load_chunk(0); load_chunk(1);
    for (int c = 0; c < 8; c++) {
        if (c + 2 < 8) { load_chunk(c + 2); CP_WAIT2(); }
        else if (c + 1 < 8) CP_WAIT1();
        else CP_WAIT0();
        __syncthreads();
        compute_chunk(c);
        __syncthreads();
    }

    float* dst = &g_part[(long)kz * (ROWS_ * EE_)];
    #pragma unroll
    for (int mt = 0; mt < 4; mt++)
        #pragma unroll
        for (int nt = 0; nt < 4; nt++) {
            float* c = acc[mt][nt];
            int col = n0 + wn * 32 + nt * 8 + (l & 3) * 2;
            int r0 = m0 + wm * 64 + mt * 16 + (l >> 2);
            *(float2*)&dst[(long)r0 * EE_ + col] = make_float2(c[0], c[1]);
            *(float2*)&dst[(long)(r0 + 8) * EE_ + col] = make_float2(c[2], c[3]);
        }
}

// ============ reduce: partials + bias + res2 -> out / LN1(carry) ==========
__global__ __launch_bounds__(256) void k_reduce_ln(const float* __restrict__ b_down,
                                                   const float* __restrict__ ln1w,
                                                   const float* __restrict__ ln1b,
                                                   float* __restrict__ out, int step) {
    int row = blockIdx.x;
    int bb = row >> 6, t = row & 63;
    int tid = threadIdx.x;
    int e = tid * 4;
    float4 v = *(const float4*)&g_part[row * EE_ + e];
    #pragma unroll
    for (int p = 1; p < 8; p++) {
        float4 q = *(const float4*)&g_part[(long)p * ROWS_ * EE_ + row * EE_ + e];
        v.x += q.x; v.y += q.y; v.z += q.z; v.w += q.w;
    }
    float4 r2 = *(const float4*)&g_res2[row * EE_ + e];
    float4 bd = *(const float4*)&b_down[e];
    v.x += r2.x + bd.x; v.y += r2.y + bd.y;
    v.z += r2.z + bd.z; v.w += r2.w + bd.w;
    if (t < ST_) {
        *(float4*)&out[((long)bb * TT_ + step * ST_ + t) * EE_ + e] = v;
    } else {
        float s = v.x + v.y + v.z + v.w;
        float s2 = v.x * v.x + v.y * v.y + v.z * v.z + v.w * v.w;
        __shared__ float ws[8], ws2[8];
        #pragma unroll
        for (int o = 16; o > 0; o >>= 1) {
            s += __shfl_xor_sync(0xffffffffu, s, o);
            s2 += __shfl_xor_sync(0xffffffffu, s2, o);
        }
        int warp = tid >> 5, lane = tid & 31;
        if (lane == 0) { ws[warp] = s; ws2[warp] = s2; }
        __syncthreads();
        if (tid < 32) {
            s = (lane < 8) ? ws[lane] : 0.f;
            s2 = (lane < 8) ? ws2[lane] : 0.f;
            #pragma unroll
            for (int o = 4; o > 0; o >>= 1) {
                s += __shfl_xor_sync(0xffffffffu, s, o);
                s2 += __shfl_xor_sync(0xffffffffu, s2, o);
            }
            if (lane == 0) { ws[0] = s; ws2[0] = s2; }
        }
        __syncthreads();
        float mu = ws[0] * (1.f / EE_);
        float var = ws2[0] * (1.f / EE_) - mu * mu;
        float rs = rsqrtf(var + 1e-5f);
        float4 wv = *(const float4*)&ln1w[e];
        float4 bv = *(const float4*)&ln1b[e];
        float4 o;
        o.x = (v.x - mu) * rs * wv.x + bv.x;
        o.y = (v.y - mu) * rs * wv.y + bv.y;
        o.z = (v.z - mu) * rs * wv.z + bv.z;
        o.w = (v.w - mu) * rs * wv.w + bv.w;
        *(float4*)&g_cn[(bb * ST_ + (t - ST_)) * EE_ + e] = o;
    }
}

// ================= launch =================
extern "C" void kernel_launch(void* const* d_in, const int* in_sizes, int n_in,
                              void* d_out, int out_size) {
    (void)in_sizes; (void)n_in; (void)out_size;
    const float* x      = (const float*)d_in[0];
    const float* ln1_w  = (const float*)d_in[1];
    const float* ln1_b  = (const float*)d_in[2];
    const float* w_fft1 = (const float*)d_in[3];
    const float* w_fft2 = (const float*)d_in[4];
    const float* ln2_w  = (const float*)d_in[5];
    const float* ln2_b  = (const float*)d_in[6];
    const float* w_up   = (const float*)d_in[7];
    const float* b_up   = (const float*)d_in[8];
    const float* w_down = (const float*)d_in[9];
    const float* b_down = (const float*)d_in[10];
    float* out = (float*)d_out;

    cudaFuncSetAttribute(k_up, cudaFuncAttributeMaxDynamicSharedMemorySize, GSMEM_);
    cudaFuncSetAttribute(k_dn, cudaFuncAttributeMaxDynamicSharedMemorySize, GSMEM_);

    __half *wup, *wdn;
    cudaGetSymbolAddress((void**)&wup, g_wup);
    cudaGetSymbolAddress((void**)&wdn, g_wdn);
    k_cvt<<<(2 * DFF_ * EE_) / 512, 256>>>(w_up, wup);
    k_cvt<<<(EE_ * DFF_) / 512, 256>>>(w_down, wdn);
    k_precompute_M<<<16, 256>>>(w_fft1, w_fft2);
    k_lnx<<<BB_ * TPAD_, 256>>>(x, ln1_w, ln1_b);
    k_prime<<<512, 256>>>();

    for (int i = 0; i < NCHUNK; i++) {
        k_fft<<<dim3(BB_, 16), 256>>>(x, i);
        k_ln2<<<ROWS_, 256>>>(ln2_w, ln2_b);
        k_up<<<dim3(2, 64), 256, GSMEM_>>>(b_up);
        k_dn<<<dim3(2, 8, 8), 256, GSMEM_>>>();
        k_reduce_ln<<<ROWS_, 256>>>(b_down, ln1_w, ln1_b, out, i);
    }
}

// round 17
// speedup vs baseline: 1.0876x; 1.0067x over previous
#include <cuda_runtime.h>
#include <cuda_fp16.h>
#include <math.h>
#include <stdint.h>

// Problem constants
#define BB_    4
#define TT_    4096
#define EE_    1024
#define DFF_   4096
#define CH_    64
#define ST_    32
#define NCHUNK 128
#define ROWS_  (BB_ * CH_)   // 256
#define TPAD_  (TT_ + ST_)   // 4128

// GEMM smem: 2 arrays (A, B), 128 rows x 64 k fp16, stride 144B,
// TRIPLE buffered.
#define RS_     144
#define ABUF_   (128 * RS_)          // 18432
#define BUFSZ_  (2 * ABUF_)          // 36864
#define GSMEM_  (3 * BUFSZ_)         // 110592

// ================= helpers =================
__device__ __forceinline__ uint32_t smem_u32(const void* p) {
    uint32_t a;
    asm("{ .reg .u64 t; cvta.to.shared.u64 t, %1; cvt.u32.u64 %0, t; }"
        : "=r"(a) : "l"(p));
    return a;
}
__device__ __forceinline__ void cp16(uint32_t d, const void* s) {
    asm volatile("cp.async.cg.shared.global [%0], [%1], 16;" :: "r"(d), "l"(s) : "memory");
}
#define CP_COMMIT() asm volatile("cp.async.commit_group;" ::: "memory")
#define CP_WAIT0()  asm volatile("cp.async.wait_group 0;" ::: "memory")
#define CP_WAIT1()  asm volatile("cp.async.wait_group 1;" ::: "memory")
#define CP_WAIT2()  asm volatile("cp.async.wait_group 2;" ::: "memory")

__device__ __forceinline__ void ldmx4(uint32_t* r, uint32_t addr) {
    asm volatile("ldmatrix.sync.aligned.m8n8.x4.shared.b16 {%0,%1,%2,%3}, [%4];"
        : "=r"(r[0]), "=r"(r[1]), "=r"(r[2]), "=r"(r[3]) : "r"(addr));
}
__device__ __forceinline__ void mma16816(float* c, const uint32_t* a, const uint32_t* b) {
    asm volatile("mma.sync.aligned.m16n8k16.row.col.f32.f16.f16.f32 "
        "{%0,%1,%2,%3}, {%4,%5,%6,%7}, {%8,%9}, {%0,%1,%2,%3};"
        : "+f"(c[0]), "+f"(c[1]), "+f"(c[2]), "+f"(c[3])
        : "r"(a[0]), "r"(a[1]), "r"(a[2]), "r"(a[3]), "r"(b[0]), "r"(b[1]));
}
__device__ __forceinline__ uint32_t pk2h(__half a, __half b) {
    __half2 t = __halves2half2(a, b);
    return *(uint32_t*)&t;
}

// ================= device scratch =================
__device__ float g_M[CH_ * CH_];
__device__ float g_cn[BB_ * ST_ * EE_];        // LN1 of carry rows
__device__ float g_cnx[BB_ * TPAD_ * EE_];     // LN1 of all x rows (precomputed)
__device__ float g_res2[ROWS_ * EE_];
__device__ float g_part[8 * ROWS_ * EE_];
__device__ __align__(16) __half g_cn2[ROWS_ * EE_];       // LN2 out, fp16 rn
__device__ __align__(16) __half g_f[ROWS_ * DFF_];        // sin-gate out, fp16 rn
__device__ __align__(16) __half g_wup[2 * DFF_ * EE_];
__device__ __align__(16) __half g_wdn[EE_ * DFF_];

// ================= setup kernels =================
__global__ void k_precompute_M(const float* __restrict__ w1,
                               const float* __restrict__ w2) {
    int idx = blockIdx.x * blockDim.x + threadIdx.x;
    int t = idx >> 6, s = idx & 63;
    float acc = 0.f;
    #pragma unroll
    for (int u = 0; u < 48; u++)
        acc += w2[t * 48 + u] * w1[u * 64 + s];
    g_M[idx] = acc;
}

__global__ void k_cvt(const float* __restrict__ src, __half* __restrict__ h) {
    int i = (blockIdx.x * blockDim.x + threadIdx.x) * 2;
    float2 v = *(const float2*)&src[i];
    *(uint32_t*)&h[i] = pk2h(__float2half_rn(v.x), __float2half_rn(v.y));
}

// LN1 of every x row (incl. 32 pad rows of zeros), once per call.
__global__ __launch_bounds__(256) void k_lnx(const float* __restrict__ x,
                                             const float* __restrict__ w,
                                             const float* __restrict__ bia) {
    int rb = blockIdx.x;                 // b * TPAD_ + gt
    int b = rb / TPAD_, gt = rb % TPAD_;
    int tid = threadIdx.x;
    float4 v = (gt < TT_) ? *(const float4*)&x[((long)b * TT_ + gt) * EE_ + 4 * tid]
                          : make_float4(0.f, 0.f, 0.f, 0.f);
    float s = v.x + v.y + v.z + v.w;
    float s2 = v.x * v.x + v.y * v.y + v.z * v.z + v.w * v.w;
    __shared__ float ws[8], ws2[8];
    #pragma unroll
    for (int o = 16; o > 0; o >>= 1) {
        s += __shfl_xor_sync(0xffffffffu, s, o);
        s2 += __shfl_xor_sync(0xffffffffu, s2, o);
    }
    int warp = tid >> 5, lane = tid & 31;
    if (lane == 0) { ws[warp] = s; ws2[warp] = s2; }
    __syncthreads();
    if (tid < 32) {
        s = (lane < 8) ? ws[lane] : 0.f;
        s2 = (lane < 8) ? ws2[lane] : 0.f;
        #pragma unroll
        for (int o = 4; o > 0; o >>= 1) {
            s += __shfl_xor_sync(0xffffffffu, s, o);
            s2 += __shfl_xor_sync(0xffffffffu, s2, o);
        }
        if (lane == 0) { ws[0] = s; ws2[0] = s2; }
    }
    __syncthreads();
    float mu = ws[0] * (1.f / EE_);
    float var = ws2[0] * (1.f / EE_) - mu * mu;
    float rs = rsqrtf(var + 1e-5f);
    float4 wv = *(const float4*)&w[4 * tid];
    float4 bv = *(const float4*)&bia[4 * tid];
    float4 o;
    o.x = (v.x - mu) * rs * wv.x + bv.x;
    o.y = (v.y - mu) * rs * wv.y + bv.y;
    o.z = (v.z - mu) * rs * wv.z + bv.z;
    o.w = (v.w - mu) * rs * wv.w + bv.w;
    *(float4*)&g_cnx[(long)rb * EE_ + 4 * tid] = o;
}

// prime g_cn for step 0
__global__ void k_prime() {
    int idx = blockIdx.x * blockDim.x + threadIdx.x;
    int b = idx >> 15, rem = idx & 32767;
    int t = rem >> 10, e = rem & 1023;
    g_cn[(b * ST_ + t) * EE_ + e] = g_cnx[((long)b * TPAD_ + t) * EE_ + e];
}

// ================= temporal mix + residual (e-sliced, smem-staged) =======
__global__ __launch_bounds__(256) void k_fft(const float* __restrict__ x, int step) {
    __shared__ float cns[64 * 64];
    __shared__ float Ms[64 * 64];
    int bb = blockIdx.x;
    int e0 = blockIdx.y * 64;
    int tid = threadIdx.x;
    #pragma unroll
    for (int i = 0; i < 4; i++) {
        int f4 = tid + i * 256;
        int s = f4 >> 4, e = (f4 & 15) * 4;
        float4 v = (s < ST_)
            ? *(const float4*)&g_cn[(bb * ST_ + s) * EE_ + e0 + e]
            : *(const float4*)&g_cnx[((long)bb * TPAD_ + step * ST_ + s) * EE_ + e0 + e];
        *(float4*)&cns[s * 64 + e] = v;
        *(float4*)&Ms[f4 * 4] = *(const float4*)&g_M[f4 * 4];
    }
    __syncthreads();
    int e = tid & 63;
    int tg = tid >> 6;
    float cr[64];
    #pragma unroll
    for (int s = 0; s < 64; s++) cr[s] = cns[s * 64 + e];
    #pragma unroll
    for (int i = 0; i < 16; i++) {
        int t = tg * 16 + i;
        float a = 0.f;
        #pragma unroll
        for (int s4 = 0; s4 < 16; s4++) {
            float4 m = *(float4*)&Ms[t * 64 + s4 * 4];
            a += m.x * cr[4 * s4] + m.y * cr[4 * s4 + 1] + m.z * cr[4 * s4 + 2] + m.w * cr[4 * s4 + 3];
        }
        int gt = step * ST_ + t;
        float resid = (gt < TT_) ? x[((long)bb * TT_ + gt) * EE_ + e0 + e] : 0.f;
        g_res2[(bb * 64 + t) * EE_ + e0 + e] = a + resid;
    }
}

// ================= LN2 (emits fp16 rn) =================
__global__ __launch_bounds__(256) void k_ln2(const float* __restrict__ w,
                                             const float* __restrict__ bia) {
    int row = blockIdx.x;
    int tid = threadIdx.x;
    float4 v = *(const float4*)&g_res2[row * EE_ + 4 * tid];
    float s = v.x + v.y + v.z + v.w;
    float s2 = v.x * v.x + v.y * v.y + v.z * v.z + v.w * v.w;
    __shared__ float ws[8], ws2[8];
    #pragma unroll
    for (int o = 16; o > 0; o >>= 1) {
        s += __shfl_xor_sync(0xffffffffu, s, o);
        s2 += __shfl_xor_sync(0xffffffffu, s2, o);
    }
    int warp = tid >> 5, lane = tid & 31;
    if (lane == 0) { ws[warp] = s; ws2[warp] = s2; }
    __syncthreads();
    if (tid < 32) {
        s = (lane < 8) ? ws[lane] : 0.f;
        s2 = (lane < 8) ? ws2[lane] : 0.f;
        #pragma unroll
        for (int o = 4; o > 0; o >>= 1) {
            s += __shfl_xor_sync(0xffffffffu, s, o);
            s2 += __shfl_xor_sync(0xffffffffu, s2, o);
        }
        if (lane == 0) { ws[0] = s; ws2[0] = s2; }
    }
    __syncthreads();
    float mu = ws[0] * (1.f / EE_);
    float var = ws2[0] * (1.f / EE_) - mu * mu;
    float rs = rsqrtf(var + 1e-5f);
    float4 wv = *(const float4*)&w[4 * tid];
    float4 bv = *(const float4*)&bia[4 * tid];
    float o0 = (v.x - mu) * rs * wv.x + bv.x;
    float o1 = (v.y - mu) * rs * wv.y + bv.y;
    float o2 = (v.z - mu) * rs * wv.z + bv.z;
    float o3 = (v.w - mu) * rs * wv.w + bv.w;
    *(uint2*)&g_cn2[row * EE_ + 4 * tid] =
        make_uint2(pk2h(__float2half_rn(o0), __float2half_rn(o1)),
                   pk2h(__float2half_rn(o2), __float2half_rn(o3)));
}

// ================= UP GEMM (fp16 1-product, 3-stage) + sin-gate ==========
// buffer layout: A at 0, B at ABUF_
__global__ __launch_bounds__(256) void k_up(const float* __restrict__ b_up) {
    extern __shared__ char smem[];
    uint32_t sb = smem_u32(smem);
    int tid = threadIdx.x, wid = tid >> 5, l = tid & 31;
    int m0 = blockIdx.x * 128;
    int gn0 = blockIdx.y * 64;
    int wm = wid & 1, wn = wid >> 1;

    uint32_t aRow = (uint32_t)(wm * 64 + (l & 7) + ((l >> 3) & 1) * 8);
    uint32_t aCol = (uint32_t)(((l >> 4) & 1) * 16);
    uint32_t bRow = (uint32_t)(wn * 32 + (l & 7) + ((l >> 4) & 1) * 8);
    uint32_t bCol = (uint32_t)(((l >> 3) & 1) * 16);

    float acc[4][4][4] = {};

    auto load_chunk = [&](int c) {
        uint32_t base = sb + (uint32_t)((c % 3) * BUFSZ_);
        int k0 = c * 64;
        #pragma unroll
        for (int i = 0; i < 4; i++) {
            int idx = tid + i * 256;
            int r = idx >> 3, seg = idx & 7;
            uint32_t d0 = base + (uint32_t)(r * RS_ + seg * 16);
            cp16(d0, &g_cn2[(m0 + r) * EE_ + k0 + seg * 8]);
            int wr = (r & 1) ? (DFF_ + gn0 + (r >> 1)) : (gn0 + (r >> 1));
            cp16(d0 + ABUF_, &g_wup[(long)wr * EE_ + k0 + seg * 8]);
        }
        CP_COMMIT();
    };
    auto compute_chunk = [&](int c) {
        uint32_t ab = sb + (uint32_t)((c % 3) * BUFSZ_);
        #pragma unroll
        for (int k0 = 0; k0 < 64; k0 += 16) {
            uint32_t a[4][4], b[2][4];
            #pragma unroll
            for (int mt = 0; mt < 4; mt++)
                ldmx4(a[mt], ab + (aRow + mt * 16) * RS_ + k0 * 2 + aCol);
            #pragma unroll
            for (int np = 0; np < 2; np++)
                ldmx4(b[np], ab + ABUF_ + (bRow + np * 16) * RS_ + k0 * 2 + bCol);
            #pragma unroll
            for (int mt = 0; mt < 4; mt++)
                #pragma unroll
                for (int nt = 0; nt < 4; nt++)
                    mma16816(acc[mt][nt], a[mt], &b[nt >> 1][(nt & 1) * 2]);
        }
    };

    load_chunk(0); load_chunk(1);
    for (int c = 0; c < 16; c++) {
        if (c + 2 < 16) { load_chunk(c + 2); CP_WAIT2(); }
        else if (c + 1 < 16) CP_WAIT1();
        else CP_WAIT0();
        __syncthreads();
        compute_chunk(c);
        __syncthreads();
    }

    // epilogue: sin-gate, stage via smem, coalesced out
    #pragma unroll
    for (int nt = 0; nt < 4; nt++) {
        int cl = wn * 16 + nt * 4 + (l & 3);
        float bg = b_up[gn0 + cl];
        float bv = b_up[DFF_ + gn0 + cl];
        #pragma unroll
        for (int mt = 0; mt < 4; mt++) {
            float* c = acc[mt][nt];
            int rl = wm * 64 + mt * 16 + (l >> 2);
            float f0 = __sinf(c[0] + bg) * (c[1] + bv);
            float f1 = __sinf(c[2] + bg) * (c[3] + bv);
            *(__half*)(smem + rl * RS_ + cl * 2) = __float2half_rn(f0);
            *(__half*)(smem + (rl + 8) * RS_ + cl * 2) = __float2half_rn(f1);
        }
    }
    __syncthreads();
    #pragma unroll
    for (int i = 0; i < 4; i++) {
        int idx = tid + i * 256;
        int r = idx >> 3, seg = idx & 7;
        uint4 vh = *(uint4*)(smem + r * RS_ + seg * 16);
        *(uint4*)&g_f[(long)(m0 + r) * DFF_ + gn0 + seg * 8] = vh;
    }
}

// ================= DOWN GEMM (fp16 1-product, split-K=8, 3-stage) ========
__global__ __launch_bounds__(256) void k_dn() {
    extern __shared__ char smem[];
    uint32_t sb = smem_u32(smem);
    int tid = threadIdx.x, wid = tid >> 5, l = tid & 31;
    int m0 = blockIdx.x * 128;
    int n0 = blockIdx.y * 128;
    int kz = blockIdx.z;
    int wm = wid & 1, wn = wid >> 1;

    uint32_t aRow = (uint32_t)(wm * 64 + (l & 7) + ((l >> 3) & 1) * 8);
    uint32_t aCol = (uint32_t)(((l >> 4) & 1) * 16);
    uint32_t bRow = (uint32_t)(wn * 32 + (l & 7) + ((l >> 4) & 1) * 8);
    uint32_t bCol = (uint32_t)(((l >> 3) & 1) * 16);

    float acc[4][4][4] = {};

    auto load_chunk = [&](int c) {
        uint32_t base = sb + (uint32_t)((c % 3) * BUFSZ_);
        int k0 = kz * 512 + c * 64;
        #pragma unroll
        for (int i = 0; i < 4; i++) {
            int idx = tid + i * 256;
            int r = idx >> 3, seg = idx & 7;
            uint32_t d0 = base + (uint32_t)(r * RS_ + seg * 16);
            cp16(d0, &g_f[(long)(m0 + r) * DFF_ + k0 + seg * 8]);
            cp16(d0 + ABUF_, &g_wdn[(long)(n0 + r) * DFF_ + k0 + seg * 8]);
        }
        CP_COMMIT();
    };
    auto compute_chunk = [&](int c) {
        uint32_t ab = sb + (uint32_t)((c % 3) * BUFSZ_);
        #pragma unroll
        for (int k0 = 0; k0 < 64; k0 += 16) {
            uint32_t a[4][4], b[2][4];
            #pragma unroll
            for (int mt = 0; mt < 4; mt++)
                ldmx4(a[mt], ab + (aRow + mt * 16) * RS_ + k0 * 2 + aCol);
            #pragma unroll
            for (int np = 0; np < 2; np++)
                ldmx4(b[np], ab + ABUF_ + (bRow + np * 16) * RS_ + k0 * 2 + bCol);
            #pragma unroll
            for (int mt = 0; mt < 4; mt++)
                #pragma unroll
                for (int nt = 0; nt < 4; nt++)
                    mma16816(acc[mt][nt], a[mt], &b[nt >> 1][(nt & 1) * 2]);
        }
    };

    load_chunk(0); load_chunk(1);
    for (int c = 0; c < 8; c++) {
        if (c + 2 < 8) { load_chunk(c + 2); CP_WAIT2(); }
        else if (c + 1 < 8) CP_WAIT1();
        else CP_WAIT0();
        __syncthreads();
        compute_chunk(c);
        __syncthreads();
    }

    float* dst = &g_part[(long)kz * (ROWS_ * EE_)];
    #pragma unroll
    for (int mt = 0; mt < 4; mt++)
        #pragma unroll
        for (int nt = 0; nt < 4; nt++) {
            float* c = acc[mt][nt];
            int col = n0 + wn * 32 + nt * 8 + (l & 3) * 2;
            int r0 = m0 + wm * 64 + mt * 16 + (l >> 2);
            *(float2*)&dst[(long)r0 * EE_ + col] = make_float2(c[0], c[1]);
            *(float2*)&dst[(long)(r0 + 8) * EE_ + col] = make_float2(c[2], c[3]);
        }
}

// ============ reduce: partials + bias + res2 -> out / LN1(carry) ==========
__global__ __launch_bounds__(256) void k_reduce_ln(const float* __restrict__ b_down,
                                                   const float* __restrict__ ln1w,
                                                   const float* __restrict__ ln1b,
                                                   float* __restrict__ out, int step) {
    int row = blockIdx.x;
    int bb = row >> 6, t = row & 63;
    int tid = threadIdx.x;
    int e = tid * 4;
    float4 v = *(const float4*)&g_part[row * EE_ + e];
    #pragma unroll
    for (int p = 1; p < 8; p++) {
        float4 q = *(const float4*)&g_part[(long)p * ROWS_ * EE_ + row * EE_ + e];
        v.x += q.x; v.y += q.y; v.z += q.z; v.w += q.w;
    }
    float4 r2 = *(const float4*)&g_res2[row * EE_ + e];
    float4 bd = *(const float4*)&b_down[e];
    v.x += r2.x + bd.x; v.y += r2.y + bd.y;
    v.z += r2.z + bd.z; v.w += r2.w + bd.w;
    if (t < ST_) {
        *(float4*)&out[((long)bb * TT_ + step * ST_ + t) * EE_ + e] = v;
    } else {
        float s = v.x + v.y + v.z + v.w;
        float s2 = v.x * v.x + v.y * v.y + v.z * v.z + v.w * v.w;
        __shared__ float ws[8], ws2[8];
        #pragma unroll
        for (int o = 16; o > 0; o >>= 1) {
            s += __shfl_xor_sync(0xffffffffu, s, o);
            s2 += __shfl_xor_sync(0xffffffffu, s2, o);
        }
        int warp = tid >> 5, lane = tid & 31;
        if (lane == 0) { ws[warp] = s; ws2[warp] = s2; }
        __syncthreads();
        if (tid < 32) {
            s = (lane < 8) ? ws[lane] : 0.f;
            s2 = (lane < 8) ? ws2[lane] : 0.f;
            #pragma unroll
            for (int o = 4; o > 0; o >>= 1) {
                s += __shfl_xor_sync(0xffffffffu, s, o);
                s2 += __shfl_xor_sync(0xffffffffu, s2, o);
            }
            if (lane == 0) { ws[0] = s; ws2[0] = s2; }
        }
        __syncthreads();
        float mu = ws[0] * (1.f / EE_);
        float var = ws2[0] * (1.f / EE_) - mu * mu;
        float rs = rsqrtf(var + 1e-5f);
        float4 wv = *(const float4*)&ln1w[e];
        float4 bv = *(const float4*)&ln1b[e];
        float4 o;
        o.x = (v.x - mu) * rs * wv.x + bv.x;
        o.y = (v.y - mu) * rs * wv.y + bv.y;
        o.z = (v.z - mu) * rs * wv.z + bv.z;
        o.w = (v.w - mu) * rs * wv.w + bv.w;
        *(float4*)&g_cn[(bb * ST_ + (t - ST_)) * EE_ + e] = o;
    }
}

// ================= launch =================
extern "C" void kernel_launch(void* const* d_in, const int* in_sizes, int n_in,
                              void* d_out, int out_size) {
    (void)in_sizes; (void)n_in; (void)out_size;
    const float* x      = (const float*)d_in[0];
    const float* ln1_w  = (const float*)d_in[1];
    const float* ln1_b  = (const float*)d_in[2];
    const float* w_fft1 = (const float*)d_in[3];
    const float* w_fft2 = (const float*)d_in[4];
    const float* ln2_w  = (const float*)d_in[5];
    const float* ln2_b  = (const float*)d_in[6];
    const float* w_up   = (const float*)d_in[7];
    const float* b_up   = (const float*)d_in[8];
    const float* w_down = (const float*)d_in[9];
    const float* b_down = (const float*)d_in[10];
    float* out = (float*)d_out;

    cudaFuncSetAttribute(k_up, cudaFuncAttributeMaxDynamicSharedMemorySize, GSMEM_);
    cudaFuncSetAttribute(k_dn, cudaFuncAttributeMaxDynamicSharedMemorySize, GSMEM_);

    __half *wup, *wdn;
    cudaGetSymbolAddress((void**)&wup, g_wup);
    cudaGetSymbolAddress((void**)&wdn, g_wdn);
    k_cvt<<<(2 * DFF_ * EE_) / 512, 256>>>(w_up, wup);
    k_cvt<<<(EE_ * DFF_) / 512, 256>>>(w_down, wdn);
    k_precompute_M<<<16, 256>>>(w_fft1, w_fft2);
    k_lnx<<<BB_ * TPAD_, 256>>>(x, ln1_w, ln1_b);
    k_prime<<<512, 256>>>();

    for (int i = 0; i < NCHUNK; i++) {
        k_fft<<<dim3(BB_, 16), 256>>>(x, i);
        k_ln2<<<ROWS_, 256>>>(ln2_w, ln2_b);
        k_up<<<dim3(2, 64), 256, GSMEM_>>>(b_up);
        k_dn<<<dim3(2, 8, 8), 256, GSMEM_>>>();
        k_reduce_ln<<<ROWS_, 256>>>(b_down, ln1_w, ln1_b, out, i);
    }
}